// round 16
// baseline (speedup 1.0000x reference)
#include <cuda_runtime.h>
#include <cuda_fp16.h>

// Problem constants (fixed by the reference)
#define N_NODES 100000
#define N_EDGES 50000
#define M_INC   1600000
#define D       64
#define DCH     8          // 16B chunks per fp16 row (8 lanes cover one row)
#define DC4     16         // float4 chunks per f32 row
#define MH      (M_INC / 2)
#define FCH     (N_NODES * DC4)      // total float4 chunks in out (1.6M)
#define FCH4    (FCH / 4)

// bit-cast helpers
__device__ __forceinline__ unsigned h2_as_u(__half2 h) {
    return *reinterpret_cast<unsigned*>(&h);
}
__device__ __forceinline__ __half2 u_as_h2(unsigned u) {
    return *reinterpret_cast<__half2*>(&u);
}

// ---------------------------------------------------------------------------
// Scratch (__device__ globals; allocation-free rule)
// ---------------------------------------------------------------------------
__device__ float  g_Dn[N_NODES];             // weighted node degree
__device__ float  g_Be[N_EDGES];             // edge cardinality
__device__ __half g_xh[(long)N_NODES * D];   // x in fp16
__device__ __half g_ef[(long)N_EDGES * D];   // raw edge feature sums, fp16
__device__ __half g_h [(long)N_NODES * D];   // unscaled node accumulator fp16

// ---------------------------------------------------------------------------
// K0 (prep): convert x->fp16, zero ef/h/Be/Dn. No atomics.
// ---------------------------------------------------------------------------
__global__ void k_prep(const float* __restrict__ x) {
    long i = blockIdx.x * (long)blockDim.x + threadIdx.x;
    long stride = (long)gridDim.x * blockDim.x;

    const long XH8 = (long)N_NODES * D / 8;
    for (long j = i; j < XH8; j += stride) {
        float4 a = ((const float4*)x)[j * 2];
        float4 b = ((const float4*)x)[j * 2 + 1];
        uint4 u;
        u.x = h2_as_u(__floats2half2_rn(a.x, a.y));
        u.y = h2_as_u(__floats2half2_rn(a.z, a.w));
        u.z = h2_as_u(__floats2half2_rn(b.x, b.y));
        u.w = h2_as_u(__floats2half2_rn(b.z, b.w));
        ((uint4*)g_xh)[j] = u;
    }

    const long EF8 = (long)N_EDGES * D / 8;
    const long H8  = (long)N_NODES * D / 8;
    uint4 z = make_uint4(0u, 0u, 0u, 0u);
    for (long j = i; j < EF8; j += stride) ((uint4*)g_ef)[j] = z;
    for (long j = i; j < H8;  j += stride) ((uint4*)g_h)[j]  = z;
    for (long j = i; j < N_NODES; j += stride) g_Dn[j] = 0.f;
    for (long j = i; j < N_EDGES; j += stride) g_Be[j] = 0.f;
}

// ---------------------------------------------------------------------------
// K1: stage 1 — scatter ef[e] += xh[n] (raw fp16x2 vector REDG).
// thread t -> 16B chunk c = t&7, incidences m0 = t>>3 and m1 = m0 + M/2.
// Side-work spread across lanes: c==0 counts Be, c==1 accumulates Dn.
// ---------------------------------------------------------------------------
__global__ void k_stage1(const int* __restrict__ ni, const int* __restrict__ ei,
                         const float* __restrict__ w) {
    int t = blockIdx.x * blockDim.x + threadIdx.x;
    if (t >= MH * DCH) return;
    int c  = t & 7;
    int m0 = t >> 3;
    int m1 = m0 + MH;

    int n0 = __ldg(&ni[m0]);
    int e0 = __ldg(&ei[m0]);
    int n1 = __ldg(&ni[m1]);
    int e1 = __ldg(&ei[m1]);

    uint4 u0 = __ldg(&((const uint4*)g_xh)[(long)n0 * DCH + c]);
    uint4 u1 = __ldg(&((const uint4*)g_xh)[(long)n1 * DCH + c]);

    __half* d0 = &g_ef[(long)e0 * D + c * 8];
    __half* d1 = &g_ef[(long)e1 * D + c * 8];
    asm volatile("red.global.add.noftz.v4.f16x2 [%0], {%1,%2,%3,%4};"
                 :: "l"(d0), "r"(u0.x), "r"(u0.y), "r"(u0.z), "r"(u0.w) : "memory");
    asm volatile("red.global.add.noftz.v4.f16x2 [%0], {%1,%2,%3,%4};"
                 :: "l"(d1), "r"(u1.x), "r"(u1.y), "r"(u1.z), "r"(u1.w) : "memory");

    if (c == 0) {
        atomicAdd(&g_Be[e0], 1.0f);
        atomicAdd(&g_Be[e1], 1.0f);
    } else if (c == 1) {
        float w0 = __ldg(&w[e0]);
        float w1 = __ldg(&w[e1]);
        atomicAdd(&g_Dn[n0], w0);
        atomicAdd(&g_Dn[n1], w1);
    }
}

// ---------------------------------------------------------------------------
// K2: stage 2 — h[n] += (1/Be[e]) * ef[e], recip inline (MUFU idle;
// Be[e] is an L1-broadcast load across the 8 lanes of an edge).
// ---------------------------------------------------------------------------
__global__ void k_stage2(const int* __restrict__ ni, const int* __restrict__ ei) {
    int t = blockIdx.x * blockDim.x + threadIdx.x;
    if (t >= MH * DCH) return;
    int c  = t & 7;
    int m0 = t >> 3;
    int m1 = m0 + MH;

    int n0 = __ldg(&ni[m0]);
    int e0 = __ldg(&ei[m0]);
    int n1 = __ldg(&ni[m1]);
    int e1 = __ldg(&ei[m1]);

    float b0 = g_Be[e0];
    float b1 = g_Be[e1];
    float br0 = (b0 > 0.f) ? __frcp_rn(b0) : 0.f;
    float br1 = (b1 > 0.f) ? __frcp_rn(b1) : 0.f;
    __half2 r0 = __float2half2_rn(br0);
    __half2 r1 = __float2half2_rn(br1);

    uint4 u0 = __ldg(&((const uint4*)g_ef)[(long)e0 * DCH + c]);
    uint4 u1 = __ldg(&((const uint4*)g_ef)[(long)e1 * DCH + c]);

    u0.x = h2_as_u(__hmul2(u_as_h2(u0.x), r0));
    u0.y = h2_as_u(__hmul2(u_as_h2(u0.y), r0));
    u0.z = h2_as_u(__hmul2(u_as_h2(u0.z), r0));
    u0.w = h2_as_u(__hmul2(u_as_h2(u0.w), r0));
    u1.x = h2_as_u(__hmul2(u_as_h2(u1.x), r1));
    u1.y = h2_as_u(__hmul2(u_as_h2(u1.y), r1));
    u1.z = h2_as_u(__hmul2(u_as_h2(u1.z), r1));
    u1.w = h2_as_u(__hmul2(u_as_h2(u1.w), r1));

    __half* d0 = &g_h[(long)n0 * D + c * 8];
    __half* d1 = &g_h[(long)n1 * D + c * 8];
    asm volatile("red.global.add.noftz.v4.f16x2 [%0], {%1,%2,%3,%4};"
                 :: "l"(d0), "r"(u0.x), "r"(u0.y), "r"(u0.z), "r"(u0.w) : "memory");
    asm volatile("red.global.add.noftz.v4.f16x2 [%0], {%1,%2,%3,%4};"
                 :: "l"(d1), "r"(u1.x), "r"(u1.y), "r"(u1.z), "r"(u1.w) : "memory");
}

// ---------------------------------------------------------------------------
// K3: final — out = 0.5*xh + (0.5/Dn)*h. 4 independent chunks per thread
// (quarter-split mapping): all loads issued before any compute/store.
// chunk = one float4 of out = one uint2 of xh = one uint2 of h.
// ---------------------------------------------------------------------------
__global__ void k_final(float* __restrict__ out) {
    int t = blockIdx.x * blockDim.x + threadIdx.x;
    if (t >= FCH4) return;

    int tt[4];
    tt[0] = t;
    tt[1] = t + FCH4;
    tt[2] = t + 2 * FCH4;
    tt[3] = t + 3 * FCH4;

    // issue all loads up front (independent chains)
    float dnv[4];
    uint2 xu[4], hu[4];
    #pragma unroll
    for (int q = 0; q < 4; q++) {
        dnv[q] = g_Dn[tt[q] >> 4];
        xu[q]  = ((const uint2*)g_xh)[tt[q]];
        hu[q]  = ((const uint2*)g_h)[tt[q]];
    }

    #pragma unroll
    for (int q = 0; q < 4; q++) {
        float dn = (dnv[q] > 0.f) ? (0.5f / dnv[q]) : 0.f;
        float2 x01 = __half22float2(u_as_h2(xu[q].x));
        float2 x23 = __half22float2(u_as_h2(xu[q].y));
        float2 h01 = __half22float2(u_as_h2(hu[q].x));
        float2 h23 = __half22float2(u_as_h2(hu[q].y));
        float4 o;
        o.x = 0.5f * x01.x + dn * h01.x;
        o.y = 0.5f * x01.y + dn * h01.y;
        o.z = 0.5f * x23.x + dn * h23.x;
        o.w = 0.5f * x23.y + dn * h23.y;
        ((float4*)out)[tt[q]] = o;
    }
}

// ---------------------------------------------------------------------------
extern "C" void kernel_launch(void* const* d_in, const int* in_sizes, int n_in,
                              void* d_out, int out_size) {
    const float* x  = (const float*)d_in[0];
    const int*   ni = (const int*)d_in[1];
    const int*   ei = (const int*)d_in[2];
    const float* w  = (const float*)d_in[3];
    float* out = (float*)d_out;

    const int T = 256;
    int stage_threads = MH * DCH;                 // 6.4M threads

    k_prep<<<2048, T>>>(x);
    k_stage1<<<(stage_threads + T - 1) / T, T>>>(ni, ei, w);
    k_stage2<<<(stage_threads + T - 1) / T, T>>>(ni, ei);
    k_final<<<(FCH4 + T - 1) / T, T>>>(out);
}

// round 17
// speedup vs baseline: 1.0235x; 1.0235x over previous
#include <cuda_runtime.h>
#include <cuda_fp16.h>

// Problem constants (fixed by the reference)
#define N_NODES 100000
#define N_EDGES 50000
#define M_INC   1600000
#define D       64
#define DCH     8          // 16B chunks per fp16 row (8 lanes cover one row)
#define DC4     16         // float4 chunks per f32 row
#define MH      (M_INC / 2)
#define FCH     (N_NODES * DC4)      // total float4 chunks in out (1.6M)
#define FCH2    (FCH / 2)

// bit-cast helpers
__device__ __forceinline__ unsigned h2_as_u(__half2 h) {
    return *reinterpret_cast<unsigned*>(&h);
}
__device__ __forceinline__ __half2 u_as_h2(unsigned u) {
    return *reinterpret_cast<__half2*>(&u);
}

// ---------------------------------------------------------------------------
// Scratch (__device__ globals; allocation-free rule)
// ---------------------------------------------------------------------------
__device__ float  g_Dn[N_NODES];             // weighted node degree
__device__ float  g_Be[N_EDGES];             // edge cardinality
__device__ __half g_xh[(long)N_NODES * D];   // x in fp16
__device__ __half g_ef[(long)N_EDGES * D];   // raw edge feature sums, fp16
__device__ __half g_h [(long)N_NODES * D];   // unscaled node accumulator fp16

// ---------------------------------------------------------------------------
// K0 (prep): convert x->fp16, zero ef/h/Be/Dn. No atomics.
// ---------------------------------------------------------------------------
__global__ void k_prep(const float* __restrict__ x) {
    long i = blockIdx.x * (long)blockDim.x + threadIdx.x;
    long stride = (long)gridDim.x * blockDim.x;

    const long XH8 = (long)N_NODES * D / 8;
    for (long j = i; j < XH8; j += stride) {
        float4 a = ((const float4*)x)[j * 2];
        float4 b = ((const float4*)x)[j * 2 + 1];
        uint4 u;
        u.x = h2_as_u(__floats2half2_rn(a.x, a.y));
        u.y = h2_as_u(__floats2half2_rn(a.z, a.w));
        u.z = h2_as_u(__floats2half2_rn(b.x, b.y));
        u.w = h2_as_u(__floats2half2_rn(b.z, b.w));
        ((uint4*)g_xh)[j] = u;
    }

    const long EF8 = (long)N_EDGES * D / 8;
    const long H8  = (long)N_NODES * D / 8;
    uint4 z = make_uint4(0u, 0u, 0u, 0u);
    for (long j = i; j < EF8; j += stride) ((uint4*)g_ef)[j] = z;
    for (long j = i; j < H8;  j += stride) ((uint4*)g_h)[j]  = z;
    for (long j = i; j < N_NODES; j += stride) g_Dn[j] = 0.f;
    for (long j = i; j < N_EDGES; j += stride) g_Be[j] = 0.f;
}

// ---------------------------------------------------------------------------
// K1: stage 1 — scatter ef[e] += xh[n] (raw fp16x2 vector REDG).
// thread t -> 16B chunk c = t&7, incidences m0 = t>>3 and m1 = m0 + M/2.
// 8 consecutive lanes cover one 128B row contiguously (coalesced).
// Side-work spread across lanes: c==0 counts Be, c==1 accumulates Dn.
// ---------------------------------------------------------------------------
__global__ void k_stage1(const int* __restrict__ ni, const int* __restrict__ ei,
                         const float* __restrict__ w) {
    int t = blockIdx.x * blockDim.x + threadIdx.x;
    if (t >= MH * DCH) return;
    int c  = t & 7;
    int m0 = t >> 3;
    int m1 = m0 + MH;

    int n0 = __ldg(&ni[m0]);
    int e0 = __ldg(&ei[m0]);
    int n1 = __ldg(&ni[m1]);
    int e1 = __ldg(&ei[m1]);

    uint4 u0 = __ldg(&((const uint4*)g_xh)[(long)n0 * DCH + c]);
    uint4 u1 = __ldg(&((const uint4*)g_xh)[(long)n1 * DCH + c]);

    __half* d0 = &g_ef[(long)e0 * D + c * 8];
    __half* d1 = &g_ef[(long)e1 * D + c * 8];
    asm volatile("red.global.add.noftz.v4.f16x2 [%0], {%1,%2,%3,%4};"
                 :: "l"(d0), "r"(u0.x), "r"(u0.y), "r"(u0.z), "r"(u0.w) : "memory");
    asm volatile("red.global.add.noftz.v4.f16x2 [%0], {%1,%2,%3,%4};"
                 :: "l"(d1), "r"(u1.x), "r"(u1.y), "r"(u1.z), "r"(u1.w) : "memory");

    if (c == 0) {
        atomicAdd(&g_Be[e0], 1.0f);
        atomicAdd(&g_Be[e1], 1.0f);
    } else if (c == 1) {
        float w0 = __ldg(&w[e0]);
        float w1 = __ldg(&w[e1]);
        atomicAdd(&g_Dn[n0], w0);
        atomicAdd(&g_Dn[n1], w1);
    }
}

// ---------------------------------------------------------------------------
// K2: stage 2 — h[n] += (1/Be[e]) * ef[e], recip inline (MUFU idle;
// Be[e] is an L1-broadcast load across the 8 lanes of an edge).
// ---------------------------------------------------------------------------
__global__ void k_stage2(const int* __restrict__ ni, const int* __restrict__ ei) {
    int t = blockIdx.x * blockDim.x + threadIdx.x;
    if (t >= MH * DCH) return;
    int c  = t & 7;
    int m0 = t >> 3;
    int m1 = m0 + MH;

    int n0 = __ldg(&ni[m0]);
    int e0 = __ldg(&ei[m0]);
    int n1 = __ldg(&ni[m1]);
    int e1 = __ldg(&ei[m1]);

    float b0 = g_Be[e0];
    float b1 = g_Be[e1];
    float br0 = (b0 > 0.f) ? __frcp_rn(b0) : 0.f;
    float br1 = (b1 > 0.f) ? __frcp_rn(b1) : 0.f;
    __half2 r0 = __float2half2_rn(br0);
    __half2 r1 = __float2half2_rn(br1);

    uint4 u0 = __ldg(&((const uint4*)g_ef)[(long)e0 * DCH + c]);
    uint4 u1 = __ldg(&((const uint4*)g_ef)[(long)e1 * DCH + c]);

    u0.x = h2_as_u(__hmul2(u_as_h2(u0.x), r0));
    u0.y = h2_as_u(__hmul2(u_as_h2(u0.y), r0));
    u0.z = h2_as_u(__hmul2(u_as_h2(u0.z), r0));
    u0.w = h2_as_u(__hmul2(u_as_h2(u0.w), r0));
    u1.x = h2_as_u(__hmul2(u_as_h2(u1.x), r1));
    u1.y = h2_as_u(__hmul2(u_as_h2(u1.y), r1));
    u1.z = h2_as_u(__hmul2(u_as_h2(u1.z), r1));
    u1.w = h2_as_u(__hmul2(u_as_h2(u1.w), r1));

    __half* d0 = &g_h[(long)n0 * D + c * 8];
    __half* d1 = &g_h[(long)n1 * D + c * 8];
    asm volatile("red.global.add.noftz.v4.f16x2 [%0], {%1,%2,%3,%4};"
                 :: "l"(d0), "r"(u0.x), "r"(u0.y), "r"(u0.z), "r"(u0.w) : "memory");
    asm volatile("red.global.add.noftz.v4.f16x2 [%0], {%1,%2,%3,%4};"
                 :: "l"(d1), "r"(u1.x), "r"(u1.y), "r"(u1.z), "r"(u1.w) : "memory");
}

// ---------------------------------------------------------------------------
// K3: final — out = 0.5*xh + (0.5/Dn)*h. 2 independent chunks per thread;
// out stores use evict-first streaming (write-once, never re-read).
// chunk = one float4 of out = one uint2 of xh = one uint2 of h.
// ---------------------------------------------------------------------------
__global__ void k_final(float* __restrict__ out) {
    int t = blockIdx.x * blockDim.x + threadIdx.x;
    if (t >= FCH2) return;

    int t0 = t;
    int t1 = t + FCH2;
    int node0 = t0 >> 4;
    int node1 = t1 >> 4;

    // issue all loads up front (independent chains)
    float dnv0 = g_Dn[node0];
    float dnv1 = g_Dn[node1];
    uint2 xu0 = ((const uint2*)g_xh)[t0];
    uint2 xu1 = ((const uint2*)g_xh)[t1];
    uint2 hu0 = ((const uint2*)g_h)[t0];
    uint2 hu1 = ((const uint2*)g_h)[t1];

    float dn0 = (dnv0 > 0.f) ? (0.5f / dnv0) : 0.f;
    float dn1 = (dnv1 > 0.f) ? (0.5f / dnv1) : 0.f;

    float2 x01 = __half22float2(u_as_h2(xu0.x));
    float2 x23 = __half22float2(u_as_h2(xu0.y));
    float2 h01 = __half22float2(u_as_h2(hu0.x));
    float2 h23 = __half22float2(u_as_h2(hu0.y));
    float4 o0;
    o0.x = 0.5f * x01.x + dn0 * h01.x;
    o0.y = 0.5f * x01.y + dn0 * h01.y;
    o0.z = 0.5f * x23.x + dn0 * h23.x;
    o0.w = 0.5f * x23.y + dn0 * h23.y;
    __stcs(&((float4*)out)[t0], o0);

    float2 y01 = __half22float2(u_as_h2(xu1.x));
    float2 y23 = __half22float2(u_as_h2(xu1.y));
    float2 g01 = __half22float2(u_as_h2(hu1.x));
    float2 g23 = __half22float2(u_as_h2(hu1.y));
    float4 o1;
    o1.x = 0.5f * y01.x + dn1 * g01.x;
    o1.y = 0.5f * y01.y + dn1 * g01.y;
    o1.z = 0.5f * y23.x + dn1 * g23.x;
    o1.w = 0.5f * y23.y + dn1 * g23.y;
    __stcs(&((float4*)out)[t1], o1);
}

// ---------------------------------------------------------------------------
extern "C" void kernel_launch(void* const* d_in, const int* in_sizes, int n_in,
                              void* d_out, int out_size) {
    const float* x  = (const float*)d_in[0];
    const int*   ni = (const int*)d_in[1];
    const int*   ei = (const int*)d_in[2];
    const float* w  = (const float*)d_in[3];
    float* out = (float*)d_out;

    const int T = 256;
    int stage_threads = MH * DCH;                 // 6.4M threads

    k_prep<<<2048, T>>>(x);
    k_stage1<<<(stage_threads + T - 1) / T, T>>>(ni, ei, w);
    k_stage2<<<(stage_threads + T - 1) / T, T>>>(ni, ei);
    k_final<<<(FCH2 + T - 1) / T, T>>>(out);
}